// round 12
// baseline (speedup 1.0000x reference)
#include <cuda_runtime.h>
#include <cuda_bf16.h>

#define BB 512
#define SS 1024
#define TT 64

typedef unsigned long long u64;

// ---- packed f32x2 helpers (Blackwell FFMA2 path) ----
__device__ __forceinline__ u64 fma2(u64 a, u64 b, u64 c) {
    u64 d;
    asm("fma.rn.f32x2 %0, %1, %2, %3;" : "=l"(d) : "l"(a), "l"(b), "l"(c));
    return d;
}
__device__ __forceinline__ u64 add2(u64 a, u64 b) {
    u64 d;
    asm("add.rn.f32x2 %0, %1, %2;" : "=l"(d) : "l"(a), "l"(b));
    return d;
}
__device__ __forceinline__ u64 pack2(float lo, float hi) {
    u64 d;
    asm("mov.b64 %0, {%1, %2};" : "=l"(d) : "f"(lo), "f"(hi));
    return d;
}
__device__ __forceinline__ void unpack2(u64 v, float& lo, float& hi) {
    asm("mov.b64 {%0, %1}, %2;" : "=f"(lo), "=f"(hi) : "l"(v));
}

// mask dtype modes
#define MM_I32 0
#define MM_F32 1
#define MM_U8  2

__device__ __forceinline__ int mask_at(const void* m, long long idx, int mode) {
    if (mode == MM_I32) return ((const int*)m)[idx] != 0;
    if (mode == MM_F32) return ((const float*)m)[idx] != 0.0f;
    return ((const unsigned char*)m)[idx] != 0;
}

// group-local barrier: 64 threads of group g sync on named barrier g+1 (IDs 1..8)
#define GBAR() asm volatile("bar.sync %0, 64;" :: "r"(g + 1) : "memory")
// seq barrier: 128 threads (fwd+bwd groups of one sequence), IDs 9..12
#define SBAR() asm volatile("bar.sync %0, 128;" :: "r"(seq + 9) : "memory")

__global__ __launch_bounds__(512, 1)
void crf_loss_kernel(const int* __restrict__ tags,
                     const void* __restrict__ mask,
                     const float* __restrict__ emit,
                     const float* __restrict__ trans,
                     float* __restrict__ out) {
    // per-group state (8 groups/block)
    __shared__ __align__(16) float p_s[8][2][TT];
    __shared__ float wm_s[8];         // scalar normalizer publish per group
    __shared__ float red_s[8][2];
    __shared__ int   lred[8][2];
    __shared__ float tsred[4][2];     // per seq (written by fwd group)
    __shared__ float comb_w[4][TT];   // bwd final vector per seq
    __shared__ float comb_mb[4];      // bwd final normalizer per seq

    const int tid  = threadIdx.x;
    const int g    = tid >> 6;        // group 0..7; warps {2g,2g+1}; even g -> SMSPs{0,1}, odd -> {2,3}
    const int seq  = g >> 1;          // sequence slot 0..3
    const int bwd  = g & 1;           // 0 = forward half, 1 = backward half
    const int tp   = tid & 63;        // owned state column
    const int wid  = tp >> 5;
    const int lane = tp & 31;

    // 4 sequences per block, length-mixed so companions of the longest die early.
    // lengths sorted descending by batch rank.
    const int bid = blockIdx.x;       // 0..127
    int b;
    if      (seq == 0) b = bid;            // ranks   0..127 (longest)
    else if (seq == 1) b = 128 + bid;      // ranks 128..255
    else if (seq == 2) b = 383 - bid;      // ranks 256..383
    else               b = 511 - bid;      // ranks 384..511 (shortest)

    const float* emitb = emit + (size_t)b * SS * TT;
    const int*   tagsb = tags + b * SS;

    // ---- decode mask storage dtype from first word (mask[0,0..] are 1s) ----
    const int w0 = ((const int*)mask)[0];
    const int mmode = (w0 == 1) ? MM_I32 : ((w0 == 0x3F800000) ? MM_F32 : MM_U8);

    // ---- sequence length = popcount of prefix mask row ----
    int cnt = 0;
    for (int s = tp; s < SS; s += 64)
        cnt += mask_at(mask, (long long)b * SS + s, mmode);
    #pragma unroll
    for (int o = 16; o; o >>= 1) cnt += __shfl_xor_sync(0xFFFFFFFFu, cnt, o);
    if (lane == 0) lred[g][wid] = cnt;
    GBAR();
    const int len = lred[g][0] + lred[g][1];

    // split point: fwd covers steps 1..m, bwd covers len-1-m steps from the far end
    const int m  = (len - 1) >> 1;
    const int M  = bwd ? (len - 1 - m) : m;     // my step count
    const int strd = bwd ? -TT : TT;
    const float* eP = emitb + (size_t)(bwd ? (len - 1) : 0) * TT + tp;  // e at step j: eP[j*strd]

    // ---- total_score (fwd group only) ----
    if (!bwd) {
        float ts = 0.0f;
        for (int s = tp; s < len; s += 64) {
            int tg = tagsb[s];
            ts += emitb[(size_t)s * TT + tg];
            if (s > 0) ts += trans[tagsb[s - 1] * TT + tg];
        }
        #pragma unroll
        for (int o = 16; o; o >>= 1) ts += __shfl_xor_sync(0xFFFFFFFFu, ts, o);
        if (lane == 0) tsred[seq][wid] = ts;
    }

    // ---- E operand in registers, packed over pairs.
    // fwd: column tp over row pairs; bwd: row tp over column pairs.
    u64 E2[32];
    #pragma unroll
    for (int j = 0; j < 32; j++) {
        float lo, hi;
        if (!bwd) {
            lo = __expf(trans[(2 * j)     * TT + tp]);
            hi = __expf(trans[(2 * j + 1) * TT + tp]);
        } else {
            lo = __expf(trans[tp * TT + 2 * j]);
            hi = __expf(trans[tp * TT + 2 * j + 1]);
        }
        E2[j] = pack2(lo, hi);
    }

    // ---- init: v0 = exp(e0 - m0), m0 = exact group max of e0 ----
    float d0v = eP[0];
    {
        float wm = d0v;
        #pragma unroll
        for (int o = 16; o; o >>= 1) wm = fmaxf(wm, __shfl_xor_sync(0xFFFFFFFFu, wm, o));
        if (lane == 0) red_s[g][wid] = wm;
    }
    GBAR();
    float m_use = fmaxf(red_s[g][0], red_s[g][1]);
    float mb    = m_use;
    float p_val = __expf(d0v - m_use);
    p_s[g][0][tp] = p_val;
    GBAR();                           // publish p_s[g][0]

    // ---- distance-8 emit prefetch ring: slot k holds e for step s with (s-1)&7==k ----
    float e_buf[8];
    #pragma unroll
    for (int i = 0; i < 8; i++)
        e_buf[i] = (1 + i <= M) ? eP[(long long)(1 + i) * strd] : 0.0f;

    int buf = 0;
    bool pending = false;

    // one step (identical fwd/bwd); KK=(s-1)&7 static in unrolled loop.
    #define CRF_STEP(S, KK, PREFETCH, PUB)                                           \
    {                                                                                \
        if (pending) { m_use = wm_s[g]; pending = false; }                           \
        float e = e_buf[(KK)];                                                       \
        if (PREFETCH)                                                                \
            e_buf[(KK)] = ((S) + 8 <= M) ? eP[(long long)((S) + 8) * strd] : 0.0f;   \
        float sc = __expf(mb + e - m_use);                                           \
        const ulonglong2* pp = (const ulonglong2*)p_s[g][buf];                       \
        u64 a0 = 0ull, a1 = 0ull, a2 = 0ull, a3 = 0ull;                              \
        u64 a4 = 0ull, a5 = 0ull, a6 = 0ull, a7 = 0ull;                              \
        _Pragma("unroll")                                                            \
        for (int j = 0; j < 32; j += 8) {                                            \
            ulonglong2 v0 = pp[(j >> 1)];                                            \
            ulonglong2 v1 = pp[(j >> 1) + 1];                                        \
            ulonglong2 v2 = pp[(j >> 1) + 2];                                        \
            ulonglong2 v3 = pp[(j >> 1) + 3];                                        \
            a0 = fma2(v0.x, E2[j],     a0);                                          \
            a1 = fma2(v0.y, E2[j + 1], a1);                                          \
            a2 = fma2(v1.x, E2[j + 2], a2);                                          \
            a3 = fma2(v1.y, E2[j + 3], a3);                                          \
            a4 = fma2(v2.x, E2[j + 4], a4);                                          \
            a5 = fma2(v2.y, E2[j + 5], a5);                                          \
            a6 = fma2(v3.x, E2[j + 6], a6);                                          \
            a7 = fma2(v3.y, E2[j + 7], a7);                                          \
        }                                                                            \
        u64 t0 = add2(a0, a1);                                                       \
        u64 t1 = add2(a2, a3);                                                       \
        u64 t2 = add2(a4, a5);                                                       \
        u64 t3 = add2(a6, a7);                                                       \
        u64 u0 = add2(t0, t1);                                                       \
        u64 u1 = add2(t2, t3);                                                       \
        u64 tt = add2(u0, u1);                                                       \
        float flo, fhi;                                                              \
        unpack2(tt, flo, fhi);                                                       \
        float acc = flo + fhi;                                                       \
        p_val = acc * sc;                                                            \
        p_s[g][buf ^ 1][tp] = p_val;                                                 \
        if (PUB) {                                                                   \
            if (tp == 0) wm_s[g] = mb + __logf(acc) + e;                             \
            pending = true;                                                          \
        }                                                                            \
        GBAR();                                                                      \
        mb = m_use;                                                                  \
        buf ^= 1;                                                                    \
    }

    int s = 1;
    for (; s + 7 <= M; s += 8) {
        CRF_STEP(s + 0, 0, true, false)
        CRF_STEP(s + 1, 1, true, false)
        CRF_STEP(s + 2, 2, true, false)
        CRF_STEP(s + 3, 3, true, true)
        CRF_STEP(s + 4, 4, true, false)
        CRF_STEP(s + 5, 5, true, false)
        CRF_STEP(s + 6, 6, true, false)
        CRF_STEP(s + 7, 7, true, true)
    }
    for (; s <= M; s++) {
        CRF_STEP(s, (s - 1) & 7, false, ((s & 3) == 0))
    }
    #undef CRF_STEP

    // ---- combine halves: log Z = mbf + mbw + log sum_t pf[t]*pw[t]*exp(-e_m[t]) ----
    if (bwd) {
        comb_w[seq][tp] = p_val;      // pw = exp(gamma_Mb - mbw), gamma = e + beta
        if (tp == 0) comb_mb[seq] = mb;
    }
    SBAR();
    if (!bwd) {
        float em = emitb[(size_t)m * TT + tp];
        float prod = p_val * comb_w[seq][tp] * __expf(-em);
        #pragma unroll
        for (int o = 16; o; o >>= 1) prod += __shfl_xor_sync(0xFFFFFFFFu, prod, o);
        if (lane == 0) red_s[g][wid] = prod;
        GBAR();
        if (tp == 0) {
            float logz = mb + comb_mb[seq] + __logf(red_s[g][0] + red_s[g][1]);
            float ts_total = tsred[seq][0] + tsred[seq][1];
            out[b] = logz - ts_total;   // -(total_score - log_z)
        }
    }
}

extern "C" void kernel_launch(void* const* d_in, const int* in_sizes, int n_in,
                              void* d_out, int out_size) {
    const int*   tags  = (const int*)d_in[0];
    const void*  mask  = d_in[1];
    const float* emit  = (const float*)d_in[2];
    const float* trans = (const float*)d_in[3];
    float* out = (float*)d_out;
    (void)in_sizes; (void)n_in; (void)out_size;

    crf_loss_kernel<<<BB / 4, 512>>>(tags, mask, emit, trans, out);
}

// round 14
// speedup vs baseline: 1.7428x; 1.7428x over previous
#include <cuda_runtime.h>
#include <cuda_bf16.h>

#define BB 512
#define SS 1024
#define TT 64

typedef unsigned long long u64;

// ---- packed f32x2 helpers (Blackwell FFMA2 path) ----
__device__ __forceinline__ u64 fma2(u64 a, u64 b, u64 c) {
    u64 d;
    asm("fma.rn.f32x2 %0, %1, %2, %3;" : "=l"(d) : "l"(a), "l"(b), "l"(c));
    return d;
}
__device__ __forceinline__ u64 add2(u64 a, u64 b) {
    u64 d;
    asm("add.rn.f32x2 %0, %1, %2;" : "=l"(d) : "l"(a), "l"(b));
    return d;
}
__device__ __forceinline__ u64 pack2(float lo, float hi) {
    u64 d;
    asm("mov.b64 %0, {%1, %2};" : "=l"(d) : "f"(lo), "f"(hi));
    return d;
}
__device__ __forceinline__ void unpack2(u64 v, float& lo, float& hi) {
    asm("mov.b64 {%0, %1}, %2;" : "=f"(lo), "=f"(hi) : "l"(v));
}

// mask dtype modes
#define MM_I32 0
#define MM_F32 1
#define MM_U8  2

__device__ __forceinline__ int mask_at(const void* m, long long idx, int mode) {
    if (mode == MM_I32) return ((const int*)m)[idx] != 0;
    if (mode == MM_F32) return ((const float*)m)[idx] != 0.0f;
    return ((const unsigned char*)m)[idx] != 0;
}

// group-local barrier: 64 threads of group g sync on named barrier g+1 (IDs 1..4)
#define GBAR() asm volatile("bar.sync %0, 64;" :: "r"(g + 1) : "memory")
// slot barrier: 128 threads (fwd+bwd groups of one slot), IDs 5..6
#define SBAR() asm volatile("bar.sync %0, 128;" :: "r"(slot + 5) : "memory")

__global__ __launch_bounds__(256, 1)
void crf_loss_kernel(const int* __restrict__ tags,
                     const void* __restrict__ mask,
                     const float* __restrict__ emit,
                     const float* __restrict__ trans,
                     float* __restrict__ out) {
    // per-group state (4 groups/block)
    __shared__ __align__(16) float p_s[4][2][TT];
    __shared__ float wm_s[4];         // scalar normalizer publish per group
    __shared__ float red_s[4][2];
    __shared__ int   lred[4][2];
    __shared__ float tsred[2][2];     // per slot (written by fwd group)
    __shared__ float comb_w[2][TT];   // bwd final vector per slot
    __shared__ float comb_mb[2];      // bwd final normalizer per slot

    const int tid  = threadIdx.x;
    const int g    = tid >> 6;        // group 0..3; warps {2g,2g+1}; even g -> SMSPs{0,1}, odd -> {2,3}
    const int slot = g >> 1;          // sequence slot 0..1
    const int bwd  = g & 1;           // 0 = forward half, 1 = backward half
    const int tp   = tid & 63;        // owned state column
    const int wid  = tp >> 5;
    const int lane = tp & 31;
    const int bid  = blockIdx.x;      // 0..127

    // ---- decode mask storage dtype from first word (mask[0,0..] are 1s) ----
    const int w0 = ((const int*)mask)[0];
    const int mmode = (w0 == 1) ? MM_I32 : ((w0 == 0x3F800000) ? MM_F32 : MM_U8);

    // ---- E operand in registers: direction-dependent only, loaded ONCE for both seqs.
    // fwd: column tp over row pairs; bwd: row tp over column pairs.
    u64 E2[32];
    #pragma unroll
    for (int j = 0; j < 32; j++) {
        float lo, hi;
        if (!bwd) {
            lo = __expf(trans[(2 * j)     * TT + tp]);
            hi = __expf(trans[(2 * j + 1) * TT + tp]);
        } else {
            lo = __expf(trans[tp * TT + 2 * j]);
            hi = __expf(trans[tp * TT + 2 * j + 1]);
        }
        E2[j] = pack2(lo, hi);
    }

    // Each slot processes TWO sequences sequentially; balanced ≈512 steps/slot:
    //   slot0: rank bid        (M≈512-bid), then rank 511-bid (M≈bid)
    //   slot1: rank 255-bid    (M≈257+bid), then rank 256+bid (M≈256-bid)
    // Coverage over bid∈[0,128): 0..127, 384..511, 128..255, 256..383 = all 512.
    #pragma unroll 1
    for (int it = 0; it < 2; it++) {
        SBAR();   // fence per-slot shared buffer reuse across sequence iterations

        const int b = (slot == 0) ? ((it == 0) ? bid : (BB - 1 - bid))
                                  : ((it == 0) ? (255 - bid) : (256 + bid));

        const float* emitb = emit + (size_t)b * SS * TT;
        const int*   tagsb = tags + b * SS;

        // ---- sequence length = popcount of prefix mask row ----
        int cnt = 0;
        for (int s = tp; s < SS; s += 64)
            cnt += mask_at(mask, (long long)b * SS + s, mmode);
        #pragma unroll
        for (int o = 16; o; o >>= 1) cnt += __shfl_xor_sync(0xFFFFFFFFu, cnt, o);
        if (lane == 0) lred[g][wid] = cnt;
        GBAR();
        const int len = lred[g][0] + lred[g][1];

        // split: fwd covers steps 1..m, bwd covers len-1-m steps from the far end
        const int m  = (len - 1) >> 1;
        const int M  = bwd ? (len - 1 - m) : m;     // my step count
        const int strd = bwd ? -TT : TT;
        const float* eP = emitb + (size_t)(bwd ? (len - 1) : 0) * TT + tp;

        // ---- total_score (fwd group only) ----
        if (!bwd) {
            float ts = 0.0f;
            for (int s = tp; s < len; s += 64) {
                int tg = tagsb[s];
                ts += emitb[(size_t)s * TT + tg];
                if (s > 0) ts += trans[tagsb[s - 1] * TT + tg];
            }
            #pragma unroll
            for (int o = 16; o; o >>= 1) ts += __shfl_xor_sync(0xFFFFFFFFu, ts, o);
            if (lane == 0) tsred[slot][wid] = ts;
        }

        // ---- init: v0 = exp(e0 - m0), m0 = exact group max of e0 ----
        float d0v = eP[0];
        {
            float wm = d0v;
            #pragma unroll
            for (int o = 16; o; o >>= 1) wm = fmaxf(wm, __shfl_xor_sync(0xFFFFFFFFu, wm, o));
            if (lane == 0) red_s[g][wid] = wm;
        }
        GBAR();
        float m_use = fmaxf(red_s[g][0], red_s[g][1]);
        float mb    = m_use;
        float p_val = __expf(d0v - m_use);
        p_s[g][0][tp] = p_val;
        GBAR();                       // publish p_s[g][0]

        // ---- distance-8 emit prefetch ring: slot k holds e for step s with (s-1)&7==k ----
        float e_buf[8];
        #pragma unroll
        for (int i = 0; i < 8; i++)
            e_buf[i] = (1 + i <= M) ? eP[(long long)(1 + i) * strd] : 0.0f;

        int buf = 0;
        bool pending = false;

        // one step (identical fwd/bwd); KK=(s-1)&7 static in unrolled loop.
        #define CRF_STEP(S, KK, PREFETCH, PUB)                                           \
        {                                                                                \
            if (pending) { m_use = wm_s[g]; pending = false; }                           \
            float e = e_buf[(KK)];                                                       \
            if (PREFETCH)                                                                \
                e_buf[(KK)] = ((S) + 8 <= M) ? eP[(long long)((S) + 8) * strd] : 0.0f;   \
            float sc = __expf(mb + e - m_use);                                           \
            const ulonglong2* pp = (const ulonglong2*)p_s[g][buf];                       \
            u64 a0 = 0ull, a1 = 0ull, a2 = 0ull, a3 = 0ull;                              \
            u64 a4 = 0ull, a5 = 0ull, a6 = 0ull, a7 = 0ull;                              \
            _Pragma("unroll")                                                            \
            for (int j = 0; j < 32; j += 8) {                                            \
                ulonglong2 v0 = pp[(j >> 1)];                                            \
                ulonglong2 v1 = pp[(j >> 1) + 1];                                        \
                ulonglong2 v2 = pp[(j >> 1) + 2];                                        \
                ulonglong2 v3 = pp[(j >> 1) + 3];                                        \
                a0 = fma2(v0.x, E2[j],     a0);                                          \
                a1 = fma2(v0.y, E2[j + 1], a1);                                          \
                a2 = fma2(v1.x, E2[j + 2], a2);                                          \
                a3 = fma2(v1.y, E2[j + 3], a3);                                          \
                a4 = fma2(v2.x, E2[j + 4], a4);                                          \
                a5 = fma2(v2.y, E2[j + 5], a5);                                          \
                a6 = fma2(v3.x, E2[j + 6], a6);                                          \
                a7 = fma2(v3.y, E2[j + 7], a7);                                          \
            }                                                                            \
            u64 t0 = add2(a0, a1);                                                       \
            u64 t1 = add2(a2, a3);                                                       \
            u64 t2 = add2(a4, a5);                                                       \
            u64 t3 = add2(a6, a7);                                                       \
            u64 u0 = add2(t0, t1);                                                       \
            u64 u1 = add2(t2, t3);                                                       \
            u64 tt = add2(u0, u1);                                                       \
            float flo, fhi;                                                              \
            unpack2(tt, flo, fhi);                                                       \
            float acc = flo + fhi;                                                       \
            p_val = acc * sc;                                                            \
            p_s[g][buf ^ 1][tp] = p_val;                                                 \
            if (PUB) {                                                                   \
                if (tp == 0) wm_s[g] = mb + __logf(acc) + e;                             \
                pending = true;                                                          \
            }                                                                            \
            GBAR();                                                                      \
            mb = m_use;                                                                  \
            buf ^= 1;                                                                    \
        }

        int s = 1;
        for (; s + 7 <= M; s += 8) {
            CRF_STEP(s + 0, 0, true, false)
            CRF_STEP(s + 1, 1, true, false)
            CRF_STEP(s + 2, 2, true, false)
            CRF_STEP(s + 3, 3, true, true)
            CRF_STEP(s + 4, 4, true, false)
            CRF_STEP(s + 5, 5, true, false)
            CRF_STEP(s + 6, 6, true, false)
            CRF_STEP(s + 7, 7, true, true)
        }
        for (; s <= M; s++) {
            CRF_STEP(s, (s - 1) & 7, false, ((s & 3) == 0))
        }
        #undef CRF_STEP

        // ---- combine halves: log Z = mbf + mbw + log sum_t pf[t]*pw[t]*exp(-e_m[t]) ----
        if (bwd) {
            comb_w[slot][tp] = p_val;   // pw = exp(gamma_Mb - mbw), gamma = e + beta
            if (tp == 0) comb_mb[slot] = mb;
        }
        SBAR();
        if (!bwd) {
            float em = emitb[(size_t)m * TT + tp];
            float prod = p_val * comb_w[slot][tp] * __expf(-em);
            #pragma unroll
            for (int o = 16; o; o >>= 1) prod += __shfl_xor_sync(0xFFFFFFFFu, prod, o);
            if (lane == 0) red_s[g][wid] = prod;
            GBAR();
            if (tp == 0) {
                float logz = mb + comb_mb[slot] + __logf(red_s[g][0] + red_s[g][1]);
                float ts_total = tsred[slot][0] + tsred[slot][1];
                out[b] = logz - ts_total;   // -(total_score - log_z)
            }
        }
    }
}

extern "C" void kernel_launch(void* const* d_in, const int* in_sizes, int n_in,
                              void* d_out, int out_size) {
    const int*   tags  = (const int*)d_in[0];
    const void*  mask  = d_in[1];
    const float* emit  = (const float*)d_in[2];
    const float* trans = (const float*)d_in[3];
    float* out = (float*)d_out;
    (void)in_sizes; (void)n_in; (void)out_size;

    crf_loss_kernel<<<BB / 4, 256>>>(tags, mask, emit, trans, out);
}